// round 9
// baseline (speedup 1.0000x reference)
#include <cuda_runtime.h>
#include <cuda_fp16.h>
#include <cstdint>

#define HH 56
#define WW 56
#define NPIX (4 * 56 * 56)   // 12544

// Scratch (device globals — no allocation allowed). fp16 interchange format.
__device__ __align__(16) __half g_qkv[NPIX * 384];   // [pix][3*128] (q|k|v)
__device__ __align__(16) __half g_wq[384 * 128];     // w_qkv^T  [n][k] half
__device__ __align__(16) __half g_wp[128 * 128];     // w_proj^T [n][k] half

// ---------------------------------------------------------------------------
// helpers
// ---------------------------------------------------------------------------
__device__ __forceinline__ void mma16(float* c, const uint32_t* a, const uint32_t* b) {
    asm volatile(
        "mma.sync.aligned.m16n8k16.row.col.f32.f16.f16.f32 "
        "{%0,%1,%2,%3}, {%4,%5,%6,%7}, {%8,%9}, {%0,%1,%2,%3};"
        : "+f"(c[0]), "+f"(c[1]), "+f"(c[2]), "+f"(c[3])
        : "r"(a[0]), "r"(a[1]), "r"(a[2]), "r"(a[3]), "r"(b[0]), "r"(b[1]));
}
__device__ __forceinline__ void ldm4(uint32_t* r, uint32_t addr) {
    asm volatile("ldmatrix.sync.aligned.m8n8.x4.shared.b16 {%0,%1,%2,%3}, [%4];"
                 : "=r"(r[0]), "=r"(r[1]), "=r"(r[2]), "=r"(r[3]) : "r"(addr));
}
__device__ __forceinline__ void ldm4t(uint32_t* r, uint32_t addr) {
    asm volatile("ldmatrix.sync.aligned.m8n8.x4.trans.shared.b16 {%0,%1,%2,%3}, [%4];"
                 : "=r"(r[0]), "=r"(r[1]), "=r"(r[2]), "=r"(r[3]) : "r"(addr));
}
__device__ __forceinline__ uint32_t h22u(__half2 h) {
    return *reinterpret_cast<uint32_t*>(&h);
}

// ---------------------------------------------------------------------------
// Weight prep: transpose + f32->f16.  w[k][n] -> W^T[n][k] half.
// ---------------------------------------------------------------------------
__global__ __launch_bounds__(256)
void prep_weights(const float* __restrict__ wqkv, const float* __restrict__ wproj)
{
    __shared__ float tile[32][33];
    const int bx = blockIdx.x, by = blockIdx.y;
    const float* src;
    __half* dst;
    int ldn, n0;
    if (bx < 12) { src = wqkv;  dst = g_wq; ldn = 384; n0 = bx * 32; }
    else         { src = wproj; dst = g_wp; ldn = 128; n0 = (bx - 12) * 32; }
    const int k0 = by * 32;
    const int t = threadIdx.x;
    const int r = t >> 3, c4 = (t & 7) << 2;

    float4 v = *(const float4*)(src + (size_t)(k0 + r) * ldn + n0 + c4);
    tile[r][c4] = v.x; tile[r][c4 + 1] = v.y;
    tile[r][c4 + 2] = v.z; tile[r][c4 + 3] = v.w;
    __syncthreads();

    __half2 h0 = __floats2half2_rn(tile[c4][r], tile[c4 + 1][r]);
    __half2 h1 = __floats2half2_rn(tile[c4 + 2][r], tile[c4 + 3][r]);
    uint2 o; o.x = h22u(h0); o.y = h22u(h1);
    *(uint2*)(dst + (size_t)(n0 + r) * 128 + k0 + c4) = o;
}

// ---------------------------------------------------------------------------
// Single-shot fp16 GEMM + bias (R7-validated): QKV projection only.
// ---------------------------------------------------------------------------
__global__ __launch_bounds__(256, 2)
void gemm_qkv(const float* __restrict__ Af, const __half* __restrict__ Bh,
              const float* __restrict__ bias, __half* __restrict__ Ch)
{
    constexpr int AWC = 64 * 20;
    constexpr int BWC = 128 * 20;
    constexpr int N = 384;

    extern __shared__ uint32_t smg[];
    uint32_t* sA = smg;
    uint32_t* sB = smg + 4 * AWC;

    const int t = threadIdx.x, w = t >> 5, lane = t & 31;
    const int wm = w & 3, wn = w >> 2;
    const int lr = lane >> 2, lc = lane & 3;
    const int bm = blockIdx.y * 64, bn = blockIdx.x * 128;

    {
        const int row = t >> 2, seg = t & 3;
        uint32_t* dst = sA + row * 20 + seg * 4;
        const float* Ap = Af + (size_t)(bm + row) * 128 + seg * 8;
#pragma unroll
        for (int s = 0; s < 4; s++) {
            float4 f0 = *(const float4*)(Ap + s * 32);
            float4 f1 = *(const float4*)(Ap + s * 32 + 4);
            uint4 v;
            v.x = h22u(__floats2half2_rn(f0.x, f0.y));
            v.y = h22u(__floats2half2_rn(f0.z, f0.w));
            v.z = h22u(__floats2half2_rn(f1.x, f1.y));
            v.w = h22u(__floats2half2_rn(f1.z, f1.w));
            *(uint4*)(dst + s * AWC) = v;
        }
    }
#pragma unroll
    for (int u = 0; u < 8; u++) {
        int f = t + 256 * u;
        int s = f >> 9, rem = f & 511;
        int row = rem >> 2, seg = rem & 3;
        *(uint4*)(sB + s * BWC + row * 20 + seg * 4) =
            *(const uint4*)(Bh + (size_t)(bn + row) * 128 + s * 32 + seg * 8);
    }
    __syncthreads();

    float acc[8][4];
#pragma unroll
    for (int nt = 0; nt < 8; nt++)
#pragma unroll
        for (int i = 0; i < 4; i++) acc[nt][i] = 0.f;

    const int lt = lane >> 3, rw = lane & 7;
    const uint32_t aBase = (uint32_t)__cvta_generic_to_shared(sA)
        + ((wm * 16 + ((lt & 1) << 3) + rw) * 20 + ((lt >> 1) << 2)) * 4;
    const uint32_t bBase = (uint32_t)__cvta_generic_to_shared(sB);
    int bOff[4];
#pragma unroll
    for (int p = 0; p < 4; p++)
        bOff[p] = ((wn * 64 + p * 16 + ((lt >> 1) << 3) + rw) * 20
                   + ((lt & 1) << 2)) * 4;

#pragma unroll
    for (int s = 0; s < 4; s++) {
#pragma unroll
        for (int kk = 0; kk < 2; kk++) {
            uint32_t af[4], bf[8][2];
            ldm4(af, aBase + (s * AWC + kk * 8) * 4);
#pragma unroll
            for (int p = 0; p < 4; p++) {
                uint32_t r4[4];
                ldm4(r4, bBase + bOff[p] + (s * BWC + kk * 8) * 4);
                bf[2 * p][0] = r4[0]; bf[2 * p][1] = r4[1];
                bf[2 * p + 1][0] = r4[2]; bf[2 * p + 1][1] = r4[3];
            }
#pragma unroll
            for (int nt = 0; nt < 8; nt++)
                mma16(acc[nt], af, bf[nt]);
        }
    }

#pragma unroll
    for (int nt = 0; nt < 8; nt++) {
        int c = bn + wn * 64 + nt * 8 + lc * 2;
        float b0 = bias[c], b1 = bias[c + 1];
        int r0 = bm + wm * 16 + lr;
        *(__half2*)(Ch + (size_t)r0 * N + c) =
            __floats2half2_rn(acc[nt][0] + b0, acc[nt][1] + b1);
        *(__half2*)(Ch + (size_t)(r0 + 8) * N + c) =
            __floats2half2_rn(acc[nt][2] + b0, acc[nt][3] + b1);
    }
}

// ---------------------------------------------------------------------------
// FUSED neighborhood attention + output projection.
// Block = 8x8 pixel tile of one batch, ALL 4 heads. 256 threads (8 warps).
// Warp w: head = w>>1, queries (w&1)*32 .. +32 (2 m16 tiles).
// Phase 1: streaming flash (R7-validated math) -> normalized half attn
//          written into the Q smem region in chunked GEMM-A layout.
// Phase 2: proj GEMM vs smem-resident W_proj^T -> f32 global out.
// Chunked layout: chunk s (32 halves of dim) of row r at s*CW + r*20 + word.
// ---------------------------------------------------------------------------
#define SQ_OFF 0                       // 4 x 64 x 20  = 5120  (Q, then attn)
#define SWP_OFF 5120                   // 4 x 128 x 20 = 10240 (W_proj)
#define SK_OFF 15360                   // 4 x 208 x 20 = 16640
#define SV_OFF 32000                   // 4 x 208 x 20 = 16640
#define SMW 48640                      // total words (194560 B)

__global__ __launch_bounds__(256, 1)
void natten_proj(const __half* __restrict__ qkv, const float* __restrict__ rpb,
                 const float* __restrict__ bproj, float* __restrict__ outp)
{
    extern __shared__ uint32_t sm[];
    __shared__ float rp[676];

    const int tile = blockIdx.x;             // 0..48
    const int ti = tile / 7, tj = tile % 7;
    const int b = blockIdx.y;
    const int i0 = ti * 8, j0 = tj * 8;
    const int r0 = min(max(i0 - 3, 0), HH - 14);
    const int c0 = min(max(j0 - 3, 0), WW - 14);
    const int tid = threadIdx.x;

    for (int e = tid; e < 676; e += 256) rp[e] = rpb[e];

    // Q: 64 rows x 128 halves -> chunked
#pragma unroll
    for (int e = tid; e < 1024; e += 256) {
        int row = e >> 4, rem = e & 15;
        int ch = rem >> 2, seg = rem & 3;
        size_t pix = (size_t)((b * HH + i0 + (row >> 3)) * WW + j0 + (row & 7));
        *(uint4*)(sm + SQ_OFF + ch * 1280 + row * 20 + seg * 4) =
            *(const uint4*)(qkv + pix * 384 + ch * 32 + seg * 8);
    }
    // W_proj^T: 128 rows x 128 halves -> chunked
#pragma unroll
    for (int e = tid; e < 2048; e += 256) {
        int row = e >> 4, rem = e & 15;
        int ch = rem >> 2, seg = rem & 3;
        *(uint4*)(sm + SWP_OFF + ch * 2560 + row * 20 + seg * 4) =
            *(const uint4*)(g_wp + (size_t)row * 128 + ch * 32 + seg * 8);
    }
    // K and V windows: 196 rows x 128 halves each -> chunked
    for (int e = tid; e < 3136; e += 256) {
        int row = e >> 4, rem = e & 15;
        int ch = rem >> 2, seg = rem & 3;
        int r = row / 14, c = row - r * 14;
        size_t pix = (size_t)((b * HH + r0 + r) * WW + c0 + c);
        const __half* base = qkv + pix * 384 + ch * 32 + seg * 8;
        *(uint4*)(sm + SK_OFF + ch * 4160 + row * 20 + seg * 4) =
            *(const uint4*)(base + 128);
        *(uint4*)(sm + SV_OFF + ch * 4160 + row * 20 + seg * 4) =
            *(const uint4*)(base + 256);
    }
    // zero-pad rows 196..207 of each chunk
    for (int e = tid; e < 960; e += 256) {
        int ch = e / 240, rem = e - ch * 240;
        sm[SK_OFF + ch * 4160 + 3920 + rem] = 0;
        sm[SV_OFF + ch * 4160 + 3920 + rem] = 0;
    }
    __syncthreads();

    const int w = tid >> 5, lane = tid & 31;
    const int lt = lane >> 3, rw = lane & 7;
    const int lr = lane >> 2, lc = lane & 3;
    const int head = w >> 1, mbase = (w & 1) * 32;

    const uint32_t smb = (uint32_t)__cvta_generic_to_shared(sm);

    // ---- phase 1: attention ----
    uint32_t af[2][2][4];
#pragma unroll
    for (int mt = 0; mt < 2; mt++)
#pragma unroll
        for (int kk = 0; kk < 2; kk++)
            ldm4(af[mt][kk], smb + (SQ_OFF + head * 1280
                + (mbase + mt * 16 + (lt & 1) * 8 + rw) * 20
                + (lt >> 1) * 4 + kk * 8) * 4);

    const uint32_t kBase = smb + (SK_OFF + head * 4160
        + ((lt >> 1) * 8 + rw) * 20 + (lt & 1) * 4) * 4;
    const uint32_t vBase = smb + (SV_OFF + head * 4160
        + ((((lane >> 3) & 1) * 8 + (lane & 7)) * 20 + (lane >> 4) * 4)) * 4;

    const int j = j0 + lr;
    const int kcj = min(max(j - 3, 0), WW - 7) - c0;
    const int cj = 6 - (j - c0);
    int kri_lo[2], kri_hi[2], ci_lo[2], ci_hi[2];
#pragma unroll
    for (int mt = 0; mt < 2; mt++) {
        int i_lo = i0 + (w & 1) * 4 + mt * 2, i_hi = i_lo + 1;
        kri_lo[mt] = min(max(i_lo - 3, 0), HH - 7) - r0;
        kri_hi[mt] = min(max(i_hi - 3, 0), HH - 7) - r0;
        ci_lo[mt] = 6 - (i_lo - r0);
        ci_hi[mt] = 6 - (i_hi - r0);
    }
    const float scale = 0.17677669529663687f;   // 32^-0.5
    const float* rph = rp + head * 169;

    float out[2][4][4];
#pragma unroll
    for (int mt = 0; mt < 2; mt++)
#pragma unroll
        for (int nt = 0; nt < 4; nt++)
#pragma unroll
            for (int i = 0; i < 4; i++) out[mt][nt][i] = 0.f;
    float lsum[2][2] = {{0.f, 0.f}, {0.f, 0.f}};

#pragma unroll
    for (int t2 = 0; t2 < 13; t2++) {
        float sacc[2][2][4];
#pragma unroll
        for (int mt = 0; mt < 2; mt++)
#pragma unroll
            for (int tt = 0; tt < 2; tt++)
#pragma unroll
                for (int i = 0; i < 4; i++) sacc[mt][tt][i] = 0.f;
#pragma unroll
        for (int kk = 0; kk < 2; kk++) {
            uint32_t r4[4];
            ldm4(r4, kBase + (t2 * 320 + kk * 8) * 4);
#pragma unroll
            for (int mt = 0; mt < 2; mt++) {
                mma16(sacc[mt][0], af[mt][kk], r4);
                mma16(sacc[mt][1], af[mt][kk], r4 + 2);
            }
        }
        uint32_t pa[2][4];
#pragma unroll
        for (int mt = 0; mt < 2; mt++) {
#pragma unroll
            for (int tt = 0; tt < 2; tt++) {
#pragma unroll
                for (int c = 0; c < 2; c++) {
                    int key = t2 * 16 + tt * 8 + 2 * lc + c;
                    int kr = (key * 2341) >> 15;
                    int kc = key - kr * 14;
                    bool vC = (unsigned)(kc - kcj) < 7u;
                    int cb = kc + cj;

                    bool v1 = vC && ((unsigned)(kr - kri_lo[mt]) < 7u);
                    int idx1 = min(max((kr + ci_lo[mt]) * 13 + cb, 0), 168);
                    float e1 = __expf(v1 ? fmaf(sacc[mt][tt][c], scale, rph[idx1]) : -60.f);
                    sacc[mt][tt][c] = e1;
                    lsum[mt][0] += e1;

                    bool v2 = vC && ((unsigned)(kr - kri_hi[mt]) < 7u);
                    int idx2 = min(max((kr + ci_hi[mt]) * 13 + cb, 0), 168);
                    float e2 = __expf(v2 ? fmaf(sacc[mt][tt][2 + c], scale, rph[idx2]) : -60.f);
                    sacc[mt][tt][2 + c] = e2;
                    lsum[mt][1] += e2;
                }
            }
            pa[mt][0] = h22u(__floats2half2_rn(sacc[mt][0][0], sacc[mt][0][1]));
            pa[mt][1] = h22u(__floats2half2_rn(sacc[mt][0][2], sacc[mt][0][3]));
            pa[mt][2] = h22u(__floats2half2_rn(sacc[mt][1][0], sacc[mt][1][1]));
            pa[mt][3] = h22u(__floats2half2_rn(sacc[mt][1][2], sacc[mt][1][3]));
        }
        uint32_t b0[4], b1[4];
        ldm4t(b0, vBase + t2 * 1280);
        ldm4t(b1, vBase + t2 * 1280 + 32);
#pragma unroll
        for (int mt = 0; mt < 2; mt++) {
            mma16(out[mt][0], pa[mt], b0);
            mma16(out[mt][1], pa[mt], b0 + 2);
            mma16(out[mt][2], pa[mt], b1);
            mma16(out[mt][3], pa[mt], b1 + 2);
        }
    }

    // reduce expsums over the quad, normalize, write attn to sQ region (half)
    const unsigned fm = 0xffffffffu;
#pragma unroll
    for (int mt = 0; mt < 2; mt++) {
        float l0 = lsum[mt][0], l1 = lsum[mt][1];
        l0 += __shfl_xor_sync(fm, l0, 1); l0 += __shfl_xor_sync(fm, l0, 2);
        l1 += __shfl_xor_sync(fm, l1, 1); l1 += __shfl_xor_sync(fm, l1, 2);
        float inv0 = __frcp_rn(l0), inv1 = __frcp_rn(l1);
        int wbase = SQ_OFF + head * 1280 + (mbase + mt * 16 + lr) * 20;
#pragma unroll
        for (int nt = 0; nt < 4; nt++) {
            sm[wbase + nt * 4 + lc] =
                h22u(__floats2half2_rn(out[mt][nt][0] * inv0, out[mt][nt][1] * inv0));
            sm[wbase + 160 + nt * 4 + lc] =
                h22u(__floats2half2_rn(out[mt][nt][2] * inv1, out[mt][nt][3] * inv1));
        }
    }
    __syncthreads();

    // ---- phase 2: output projection 64x128 @ Wp^T ----
    const int wm = w & 3, wn = w >> 2;
    float acc[8][4];
#pragma unroll
    for (int nt = 0; nt < 8; nt++)
#pragma unroll
        for (int i = 0; i < 4; i++) acc[nt][i] = 0.f;

    const uint32_t aBase2 = smb + (SQ_OFF
        + (wm * 16 + (lt & 1) * 8 + rw) * 20 + (lt >> 1) * 4) * 4;
    int bOff2[4];
#pragma unroll
    for (int p = 0; p < 4; p++)
        bOff2[p] = (SWP_OFF + (wn * 64 + p * 16 + (lt >> 1) * 8 + rw) * 20
                    + (lt & 1) * 4) * 4;

#pragma unroll
    for (int s = 0; s < 4; s++) {
#pragma unroll
        for (int kk = 0; kk < 2; kk++) {
            uint32_t a2[4], bf[8][2];
            ldm4(a2, aBase2 + (s * 1280 + kk * 8) * 4);
#pragma unroll
            for (int p = 0; p < 4; p++) {
                uint32_t r4[4];
                ldm4(r4, smb + bOff2[p] + (s * 2560 + kk * 8) * 4);
                bf[2 * p][0] = r4[0]; bf[2 * p][1] = r4[1];
                bf[2 * p + 1][0] = r4[2]; bf[2 * p + 1][1] = r4[3];
            }
#pragma unroll
            for (int nt = 0; nt < 8; nt++)
                mma16(acc[nt], a2, bf[nt]);
        }
    }

    // epilogue: bias + f32 store
    const int q0 = wm * 16 + lr;
    size_t pix0 = (size_t)((b * HH + i0 + wm * 2) * WW + j0 + lr);
    size_t pix1 = (size_t)((b * HH + i0 + wm * 2 + 1) * WW + j0 + lr);
    (void)q0;
#pragma unroll
    for (int nt = 0; nt < 8; nt++) {
        int c = wn * 64 + nt * 8 + lc * 2;
        float b0 = bproj[c], b1 = bproj[c + 1];
        *(float2*)(outp + pix0 * 128 + c) =
            make_float2(acc[nt][0] + b0, acc[nt][1] + b1);
        *(float2*)(outp + pix1 * 128 + c) =
            make_float2(acc[nt][2] + b0, acc[nt][3] + b1);
    }
}

// ---------------------------------------------------------------------------
// Launch
// ---------------------------------------------------------------------------
extern "C" void kernel_launch(void* const* d_in, const int* in_sizes, int n_in,
                              void* d_out, int out_size)
{
    const float* x      = (const float*)d_in[0];  // [4,56,56,128]
    const float* w_qkv  = (const float*)d_in[1];  // [128,384]
    const float* b_qkv  = (const float*)d_in[2];  // [384]
    const float* rpb    = (const float*)d_in[3];  // [4,13,13]
    const float* w_proj = (const float*)d_in[4];  // [128,128]
    const float* b_proj = (const float*)d_in[5];  // [128]
    float* out = (float*)d_out;                   // [4,56,56,128] fp32
    (void)in_sizes; (void)n_in; (void)out_size; (void)w_proj;

    __half *qkv_buf, *wq_buf;
    cudaGetSymbolAddress((void**)&qkv_buf, g_qkv);
    cudaGetSymbolAddress((void**)&wq_buf, g_wq);

    constexpr int SMG = (4 * 64 * 20 + 4 * 128 * 20) * 4;   // 61440 B
    constexpr int SMF = SMW * 4;                            // 194560 B

    cudaFuncSetAttribute(gemm_qkv,
                         cudaFuncAttributeMaxDynamicSharedMemorySize, SMG);
    cudaFuncSetAttribute(natten_proj,
                         cudaFuncAttributeMaxDynamicSharedMemorySize, SMF);

    // 0) weight prep: f32 -> half, transposed to [N][K]
    prep_weights<<<dim3(16, 4), 256>>>(w_qkv, w_proj);

    // 1) QKV projection: [12544,128] @ [128,384] + b_qkv -> half
    gemm_qkv<<<dim3(3, NPIX / 64), 256, SMG>>>(x, wq_buf, b_qkv, qkv_buf);

    // 2) Fused neighborhood attention + output projection
    natten_proj<<<dim3(49, 4), 256, SMF>>>(qkv_buf, rpb, b_proj, out);
}

// round 10
// speedup vs baseline: 1.1536x; 1.1536x over previous
#include <cuda_runtime.h>
#include <cuda_fp16.h>
#include <cstdint>

#define HH 56
#define WW 56
#define NPIX (4 * 56 * 56)   // 12544

// Scratch (device globals — no allocation allowed). fp16 interchange format.
__device__ __align__(16) __half g_qkv[NPIX * 384];   // [pix][3*128] (q|k|v)
__device__ __align__(16) __half g_att[NPIX * 128];   // attention output

// ---------------------------------------------------------------------------
// helpers
// ---------------------------------------------------------------------------
__device__ __forceinline__ void mma16(float* c, const uint32_t* a, const uint32_t* b) {
    asm volatile(
        "mma.sync.aligned.m16n8k16.row.col.f32.f16.f16.f32 "
        "{%0,%1,%2,%3}, {%4,%5,%6,%7}, {%8,%9}, {%0,%1,%2,%3};"
        : "+f"(c[0]), "+f"(c[1]), "+f"(c[2]), "+f"(c[3])
        : "r"(a[0]), "r"(a[1]), "r"(a[2]), "r"(a[3]), "r"(b[0]), "r"(b[1]));
}
__device__ __forceinline__ void ldm4(uint32_t* r, uint32_t addr) {
    asm volatile("ldmatrix.sync.aligned.m8n8.x4.shared.b16 {%0,%1,%2,%3}, [%4];"
                 : "=r"(r[0]), "=r"(r[1]), "=r"(r[2]), "=r"(r[3]) : "r"(addr));
}
__device__ __forceinline__ void ldm4t(uint32_t* r, uint32_t addr) {
    asm volatile("ldmatrix.sync.aligned.m8n8.x4.trans.shared.b16 {%0,%1,%2,%3}, [%4];"
                 : "=r"(r[0]), "=r"(r[1]), "=r"(r[2]), "=r"(r[3]) : "r"(addr));
}
__device__ __forceinline__ uint32_t h22u(__half2 h) {
    return *reinterpret_cast<uint32_t*>(&h);
}

// ---------------------------------------------------------------------------
// Single-shot fp16 GEMM + bias, no weight prep:
//   C[M,N] = A[M,128] @ W[k=128][N] + bias
// W staged to smem as [k][n-chunks of 32] halves (f32->f16 on the fly),
// B-fragments via ldmatrix.trans (the natten-AV-validated pattern).
// A staged in the validated stride-20 chunked layout.
// 256 threads, 8 warps as (MW x NW). ONE sync, unrolled sync-free mainloop.
// W chunk stride 2576 words (2560+16) => staging STS.128 phases all-32-bank.
// ---------------------------------------------------------------------------
template <int BM, int BN, bool AHALF, bool OUTHALF>
__global__ __launch_bounds__(256, 2)
void gemm_f16(const void* __restrict__ Av, const float* __restrict__ Wf,
              const float* __restrict__ bias, void* __restrict__ Cv, int N)
{
    constexpr int MW = (BM == 64) ? 4 : 2;     // warps along m
    constexpr int NW = 8 / MW;                 // warps along n
    constexpr int WN = BN / NW;                // n cols per warp (64 or 16)
    constexpr int NP = WN / 16;                // n16 tiles per warp
    constexpr int NT = WN / 8;                 // mma n tiles per warp
    constexpr int AW_TOT = 4 * BM * 20;        // A words (4 k-chunks)
    constexpr int WCS = 2576;                  // W chunk stride (words)
    constexpr int WCH = BN / 32;               // W chunks

    extern __shared__ uint32_t smg[];
    uint32_t* sA = smg;
    uint32_t* sW = smg + AW_TOT;

    const int t = threadIdx.x, w = t >> 5, lane = t & 31;
    const int wm = w % MW, wn = w / MW;
    const int lr = lane >> 2, lc = lane & 3;
    const int lt = lane >> 3, rw = lane & 7;
    const int bm = blockIdx.y * BM, bn = blockIdx.x * BN;

    // ---- stage A ----
    if constexpr (!AHALF) {
        // BM == 64 path (QKV input x, f32)
        const int row = t >> 2, seg = t & 3;
        uint32_t* dst = sA + row * 20 + seg * 4;
        const float* Ap = (const float*)Av + (size_t)(bm + row) * 128 + seg * 8;
#pragma unroll
        for (int s = 0; s < 4; s++) {
            float4 f0 = *(const float4*)(Ap + s * 32);
            float4 f1 = *(const float4*)(Ap + s * 32 + 4);
            uint4 v;
            v.x = h22u(__floats2half2_rn(f0.x, f0.y));
            v.y = h22u(__floats2half2_rn(f0.z, f0.w));
            v.z = h22u(__floats2half2_rn(f1.x, f1.y));
            v.w = h22u(__floats2half2_rn(f1.z, f1.w));
            *(uint4*)(dst + s * (BM * 20)) = v;
        }
    } else {
        constexpr int AU = (BM * 16) / 256;
        const __half* Ah = (const __half*)Av;
#pragma unroll
        for (int u = 0; u < AU; u++) {
            int f = t + 256 * u;
            int row = f >> 4, gi = f & 15;
            int ch = gi >> 2, seg = gi & 3;
            *(uint4*)(sA + ch * (BM * 20) + row * 20 + seg * 4) =
                *(const uint4*)(Ah + (size_t)(bm + row) * 128 + gi * 8);
        }
    }
    // ---- stage W [k][n] -> chunked halves ----
    {
        constexpr int WU = (128 * (BN / 8)) / 256;
#pragma unroll
        for (int u = 0; u < WU; u++) {
            int g = t + 256 * u;
            int k = g / (BN / 8), ni = g % (BN / 8);
            const float* Wp = Wf + (size_t)k * N + bn + ni * 8;
            float4 f0 = *(const float4*)(Wp);
            float4 f1 = *(const float4*)(Wp + 4);
            uint4 v;
            v.x = h22u(__floats2half2_rn(f0.x, f0.y));
            v.y = h22u(__floats2half2_rn(f0.z, f0.w));
            v.z = h22u(__floats2half2_rn(f1.x, f1.y));
            v.w = h22u(__floats2half2_rn(f1.z, f1.w));
            *(uint4*)(sW + (ni >> 2) * WCS + k * 20 + (ni & 3) * 4) = v;
        }
    }
    __syncthreads();

    // ---- mainloop: 8 k-steps, no syncs ----
    float acc[NT][4];
#pragma unroll
    for (int nt = 0; nt < NT; nt++)
#pragma unroll
        for (int i = 0; i < 4; i++) acc[nt][i] = 0.f;

    const uint32_t smb = (uint32_t)__cvta_generic_to_shared(smg);
    const uint32_t aBase = smb
        + ((wm * 16 + (lt & 1) * 8 + rw) * 20 + (lt >> 1) * 4) * 4;
    const uint32_t vpat = ((((lane >> 3) & 1) * 8 + (lane & 7)) * 20
                           + (lane >> 4) * 4) * 4;
    uint32_t bAddr[NP];
#pragma unroll
    for (int p = 0; p < NP; p++) {
        int n0 = wn * WN + p * 16;
        bAddr[p] = smb + (AW_TOT + (n0 >> 5) * WCS) * 4 + vpat
                   + ((n0 & 16) ? 32 : 0);
    }

#pragma unroll
    for (int s = 0; s < 8; s++) {
        uint32_t af[4], bf[NT][2];
        ldm4(af, aBase + (s >> 1) * (BM * 80) + (s & 1) * 32);
#pragma unroll
        for (int p = 0; p < NP; p++) {
            uint32_t r4[4];
            ldm4t(r4, bAddr[p] + s * 1280);
            bf[2 * p][0] = r4[0]; bf[2 * p][1] = r4[1];
            bf[2 * p + 1][0] = r4[2]; bf[2 * p + 1][1] = r4[3];
        }
#pragma unroll
        for (int nt = 0; nt < NT; nt++)
            mma16(acc[nt], af, bf[nt]);
    }

    // ---- epilogue with bias ----
#pragma unroll
    for (int nt = 0; nt < NT; nt++) {
        int c = bn + wn * WN + nt * 8 + lc * 2;
        float b0 = bias[c], b1 = bias[c + 1];
        int r0 = bm + wm * 16 + lr;
        if constexpr (OUTHALF) {
            __half* Ch = (__half*)Cv;
            *(__half2*)(Ch + (size_t)r0 * N + c) =
                __floats2half2_rn(acc[nt][0] + b0, acc[nt][1] + b1);
            *(__half2*)(Ch + (size_t)(r0 + 8) * N + c) =
                __floats2half2_rn(acc[nt][2] + b0, acc[nt][3] + b1);
        } else {
            float* Cf = (float*)Cv;
            *(float2*)(Cf + (size_t)r0 * N + c) =
                make_float2(acc[nt][0] + b0, acc[nt][1] + b1);
            *(float2*)(Cf + (size_t)(r0 + 8) * N + c) =
                make_float2(acc[nt][2] + b0, acc[nt][3] + b1);
        }
    }
}

// ---------------------------------------------------------------------------
// Streaming flash-style neighborhood attention (R7-validated, verbatim).
// ---------------------------------------------------------------------------
#define SQ_OFF 0
#define SK_OFF (64 * 20)
#define SV_OFF (SK_OFF + 208 * 20)
#define SM_WORDS (SV_OFF + 208 * 20)

__global__ __launch_bounds__(128)
void natten_kernel(const __half* __restrict__ qkv, const float* __restrict__ rpb)
{
    __shared__ __align__(16) uint32_t sm[SM_WORDS];
    __shared__ float rp[169];

    const int tile = blockIdx.x;             // 0..48
    const int ti = tile / 7, tj = tile % 7;
    const int h = blockIdx.y, b = blockIdx.z;
    const int i0 = ti * 8, j0 = tj * 8;
    const int r0 = min(max(i0 - 3, 0), HH - 14);
    const int c0 = min(max(j0 - 3, 0), WW - 14);
    const int tid = threadIdx.x;

    for (int e = tid; e < 169; e += 128) rp[e] = rpb[h * 169 + e];

#pragma unroll
    for (int e = tid; e < 256; e += 128) {
        int row = e >> 2, seg = e & 3;
        int qi = row >> 3, qj = row & 7;
        size_t pix = (size_t)((b * HH + i0 + qi) * WW + j0 + qj);
        *(uint4*)(sm + SQ_OFF + row * 20 + seg * 4) =
            *(const uint4*)(qkv + pix * 384 + h * 32 + seg * 8);
    }
    for (int e = tid; e < 784; e += 128) {
        int row = e >> 2, seg = e & 3;
        int r = row / 14, c = row - r * 14;
        size_t pix = (size_t)((b * HH + r0 + r) * WW + c0 + c);
        const __half* base = qkv + pix * 384 + h * 32;
        *(uint4*)(sm + SK_OFF + row * 20 + seg * 4) = *(const uint4*)(base + 128 + seg * 8);
        *(uint4*)(sm + SV_OFF + row * 20 + seg * 4) = *(const uint4*)(base + 256 + seg * 8);
    }
    for (int e = tid; e < 240; e += 128) {
        sm[SK_OFF + 3920 + e] = 0;
        sm[SV_OFF + 3920 + e] = 0;
    }
    __syncthreads();

    const int w = tid >> 5, lane = tid & 31;
    const int lr = lane >> 2, lc = lane & 3;
    const int lt = lane >> 3, rw = lane & 7;

    const uint32_t base = (uint32_t)__cvta_generic_to_shared(sm);
    const uint32_t aAddr = base + SQ_OFF * 4
        + ((w * 16 + (lt & 1) * 8 + rw) * 20 + ((lt >> 1) << 2)) * 4;
    const uint32_t kAddr = base + SK_OFF * 4
        + ((((lt >> 1) << 3) + rw) * 20 + ((lt & 1) << 2)) * 4;
    const uint32_t vAddr = base + SV_OFF * 4
        + (((((lane >> 3) & 1) << 3) + (lane & 7)) * 20 + ((lane >> 4) << 2)) * 4;

    uint32_t af0[4], af1[4];
    ldm4(af0, aAddr);
    ldm4(af1, aAddr + 32);

    const int i_lo = i0 + 2 * w, i_hi = i_lo + 1;
    const int j = j0 + lr;
    const int kri_lo = min(max(i_lo - 3, 0), HH - 7) - r0;
    const int kri_hi = min(max(i_hi - 3, 0), HH - 7) - r0;
    const int kcj = min(max(j - 3, 0), WW - 7) - c0;
    const int ci_lo = 6 - (i_lo - r0);
    const int ci_hi = 6 - (i_hi - r0);
    const int cj = 6 - (j - c0);
    const float scale = 0.17677669529663687f;   // 32^-0.5

    float out[4][4];
#pragma unroll
    for (int nt = 0; nt < 4; nt++)
#pragma unroll
        for (int i = 0; i < 4; i++) out[nt][i] = 0.f;
    float l_lo = 0.f, l_hi = 0.f;

#pragma unroll
    for (int t2 = 0; t2 < 13; t2++) {
        float sacc[2][4];
#pragma unroll
        for (int tt = 0; tt < 2; tt++)
#pragma unroll
            for (int i = 0; i < 4; i++) sacc[tt][i] = 0.f;
        {
            uint32_t r4[4];
            ldm4(r4, kAddr + t2 * 1280);
            mma16(sacc[0], af0, r4);
            mma16(sacc[1], af0, r4 + 2);
            ldm4(r4, kAddr + t2 * 1280 + 32);
            mma16(sacc[0], af1, r4);
            mma16(sacc[1], af1, r4 + 2);
        }
#pragma unroll
        for (int tt = 0; tt < 2; tt++) {
#pragma unroll
            for (int c = 0; c < 2; c++) {
                int key = (2 * t2 + tt) * 8 + 2 * lc + c;
                int kr = (key * 2341) >> 15;
                int kc = key - kr * 14;
                bool vC = (unsigned)(kc - kcj) < 7u;
                int cb = kc + cj;

                bool v1 = vC && ((unsigned)(kr - kri_lo) < 7u);
                int idx1 = min(max((kr + ci_lo) * 13 + cb, 0), 168);
                float e1 = __expf(v1 ? fmaf(sacc[tt][c], scale, rp[idx1]) : -60.f);
                sacc[tt][c] = e1;
                l_lo += e1;

                bool v2 = vC && ((unsigned)(kr - kri_hi) < 7u);
                int idx2 = min(max((kr + ci_hi) * 13 + cb, 0), 168);
                float e2 = __expf(v2 ? fmaf(sacc[tt][2 + c], scale, rp[idx2]) : -60.f);
                sacc[tt][2 + c] = e2;
                l_hi += e2;
            }
        }
        uint32_t pa[4];
        pa[0] = h22u(__floats2half2_rn(sacc[0][0], sacc[0][1]));
        pa[1] = h22u(__floats2half2_rn(sacc[0][2], sacc[0][3]));
        pa[2] = h22u(__floats2half2_rn(sacc[1][0], sacc[1][1]));
        pa[3] = h22u(__floats2half2_rn(sacc[1][2], sacc[1][3]));

        uint32_t b0[4], b1[4];
        ldm4t(b0, vAddr + t2 * 1280);
        ldm4t(b1, vAddr + t2 * 1280 + 32);
        mma16(out[0], pa, b0);
        mma16(out[1], pa, b0 + 2);
        mma16(out[2], pa, b1);
        mma16(out[3], pa, b1 + 2);
    }

    const unsigned fm = 0xffffffffu;
    l_lo += __shfl_xor_sync(fm, l_lo, 1);
    l_lo += __shfl_xor_sync(fm, l_lo, 2);
    l_hi += __shfl_xor_sync(fm, l_hi, 1);
    l_hi += __shfl_xor_sync(fm, l_hi, 2);

    const float inv_lo = __frcp_rn(l_lo);
    const float inv_hi = __frcp_rn(l_hi);
    __half* o_lo = g_att + ((size_t)((b * HH + i_lo) * WW + j)) * 128 + h * 32;
    __half* o_hi = g_att + ((size_t)((b * HH + i_hi) * WW + j)) * 128 + h * 32;
#pragma unroll
    for (int nt = 0; nt < 4; nt++) {
        *(__half2*)(o_lo + nt * 8 + 2 * lc) =
            __floats2half2_rn(out[nt][0] * inv_lo, out[nt][1] * inv_lo);
        *(__half2*)(o_hi + nt * 8 + 2 * lc) =
            __floats2half2_rn(out[nt][2] * inv_hi, out[nt][3] * inv_hi);
    }
}

// ---------------------------------------------------------------------------
// Launch
// ---------------------------------------------------------------------------
extern "C" void kernel_launch(void* const* d_in, const int* in_sizes, int n_in,
                              void* d_out, int out_size)
{
    const float* x      = (const float*)d_in[0];  // [4,56,56,128]
    const float* w_qkv  = (const float*)d_in[1];  // [128,384]
    const float* b_qkv  = (const float*)d_in[2];  // [384]
    const float* rpb    = (const float*)d_in[3];  // [4,13,13]
    const float* w_proj = (const float*)d_in[4];  // [128,128]
    const float* b_proj = (const float*)d_in[5];  // [128]
    float* out = (float*)d_out;                   // [4,56,56,128] fp32
    (void)in_sizes; (void)n_in; (void)out_size;

    __half *qkv_buf, *att_buf;
    cudaGetSymbolAddress((void**)&qkv_buf, g_qkv);
    cudaGetSymbolAddress((void**)&att_buf, g_att);

    constexpr int SMQ = (4 * 64 * 20 + 4 * 2576) * 4;   // 61696 B
    constexpr int SMP = (4 * 32 * 20 + 2 * 2576) * 4;   // 30848 B

    cudaFuncSetAttribute((const void*)gemm_f16<64, 128, false, true>,
                         cudaFuncAttributeMaxDynamicSharedMemorySize, SMQ);
    cudaFuncSetAttribute((const void*)gemm_f16<32, 64, true, false>,
                         cudaFuncAttributeMaxDynamicSharedMemorySize, SMP);

    // 1) QKV projection: [12544,128] @ [128,384] + b_qkv -> half
    gemm_f16<64, 128, false, true><<<dim3(3, NPIX / 64), 256, SMQ>>>(
        x, w_qkv, b_qkv, qkv_buf, 384);

    // 2) Neighborhood attention (streaming tensor-core flash)
    natten_kernel<<<dim3(49, 4, 4), 128>>>(qkv_buf, rpb);

    // 3) Output projection: [12544,128] @ [128,128] + b_proj -> float
    gemm_f16<32, 64, true, false><<<dim3(2, NPIX / 32), 256, SMP>>>(
        att_buf, w_proj, b_proj, out, 128);
}

// round 11
// speedup vs baseline: 1.2450x; 1.0792x over previous
#include <cuda_runtime.h>
#include <cuda_fp16.h>
#include <cstdint>

#define HH 56
#define WW 56
#define NPIX (4 * 56 * 56)   // 12544

// Scratch (device globals — no allocation allowed). fp16 interchange format.
__device__ __align__(16) __half g_qkv[NPIX * 384];   // [pix][3*128] (q|k|v)
__device__ __align__(16) __half g_att[NPIX * 128];   // attention output

// ---------------------------------------------------------------------------
// helpers
// ---------------------------------------------------------------------------
__device__ __forceinline__ void mma16(float* c, const uint32_t* a, const uint32_t* b) {
    asm volatile(
        "mma.sync.aligned.m16n8k16.row.col.f32.f16.f16.f32 "
        "{%0,%1,%2,%3}, {%4,%5,%6,%7}, {%8,%9}, {%0,%1,%2,%3};"
        : "+f"(c[0]), "+f"(c[1]), "+f"(c[2]), "+f"(c[3])
        : "r"(a[0]), "r"(a[1]), "r"(a[2]), "r"(a[3]), "r"(b[0]), "r"(b[1]));
}
__device__ __forceinline__ void ldm4(uint32_t* r, uint32_t addr) {
    asm volatile("ldmatrix.sync.aligned.m8n8.x4.shared.b16 {%0,%1,%2,%3}, [%4];"
                 : "=r"(r[0]), "=r"(r[1]), "=r"(r[2]), "=r"(r[3]) : "r"(addr));
}
__device__ __forceinline__ void ldm4t(uint32_t* r, uint32_t addr) {
    asm volatile("ldmatrix.sync.aligned.m8n8.x4.trans.shared.b16 {%0,%1,%2,%3}, [%4];"
                 : "=r"(r[0]), "=r"(r[1]), "=r"(r[2]), "=r"(r[3]) : "r"(addr));
}
__device__ __forceinline__ uint32_t h22u(__half2 h) {
    return *reinterpret_cast<uint32_t*>(&h);
}

// ---------------------------------------------------------------------------
// Persistent-column fp16 GEMM + bias:
//   C[M,N] = A[M,128] @ W[k=128][N] + bias
// Grid (N/BN, 49). Block loads its W column to smem ONCE (chunked, stride
// 2576 words, f32->f16 while staging; trans-ldmatrix B fragments — all
// R9-validated), then iterates 4 m-tiles of 64 rows with double-buffered
// A staging: STS(m) -> sync -> LDG(m+1) -> mma(m) -> epilogue(m).
// 256 threads, 8 warps as 4x2.
// ---------------------------------------------------------------------------
template <int BN, bool AHALF, bool OUTHALF>
__global__ __launch_bounds__(256, 1)
void gemm_col(const void* __restrict__ Av, const float* __restrict__ Wf,
              const float* __restrict__ bias, void* __restrict__ Cv, int N)
{
    constexpr int WN = BN / 2;                 // n cols per warp
    constexpr int NP = WN / 16;                // n16 tiles per warp
    constexpr int NT = WN / 8;                 // mma n tiles per warp
    constexpr int WCS = 2576;                  // W chunk stride (words)
    constexpr int AB = 4 * 64 * 20;            // words per A buffer (4 k-chunks)

    extern __shared__ uint32_t smg[];
    uint32_t* sA = smg;                        // 2 buffers of AB
    uint32_t* sW = smg + 2 * AB;

    const int t = threadIdx.x, w = t >> 5, lane = t & 31;
    const int wm = w & 3, wn = w >> 2;
    const int lr = lane >> 2, lc = lane & 3;
    const int lt = lane >> 3, rw = lane & 7;
    const int bn = blockIdx.x * BN;
    const int mbase = blockIdx.y * 256;        // 4 tiles of 64 rows

    // ---- stage W once: [k][n] -> chunked halves ----
    {
        constexpr int WU = (128 * (BN / 8)) / 256;
#pragma unroll
        for (int u = 0; u < WU; u++) {
            int g = t + 256 * u;
            int k = g / (BN / 8), ni = g % (BN / 8);
            const float* Wp = Wf + (size_t)k * N + bn + ni * 8;
            float4 f0 = *(const float4*)(Wp);
            float4 f1 = *(const float4*)(Wp + 4);
            uint4 v;
            v.x = h22u(__floats2half2_rn(f0.x, f0.y));
            v.y = h22u(__floats2half2_rn(f0.z, f0.w));
            v.z = h22u(__floats2half2_rn(f1.x, f1.y));
            v.w = h22u(__floats2half2_rn(f1.z, f1.w));
            *(uint4*)(sW + (ni >> 2) * WCS + k * 20 + (ni & 3) * 4) = v;
        }
    }

    // per-lane fragment addresses (R9-validated patterns)
    const uint32_t smb = (uint32_t)__cvta_generic_to_shared(smg);
    const uint32_t aPat = ((wm * 16 + (lt & 1) * 8 + rw) * 20 + (lt >> 1) * 4) * 4;
    const uint32_t vpat = ((((lane >> 3) & 1) * 8 + (lane & 7)) * 20
                           + (lane >> 4) * 4) * 4;
    uint32_t bAddr[NP];
#pragma unroll
    for (int p = 0; p < NP; p++) {
        int n0 = wn * WN + p * 16;
        bAddr[p] = smb + (2 * AB + (n0 >> 5) * WCS) * 4 + vpat
                   + ((n0 & 16) ? 32 : 0);
    }
    // bias registers (fixed columns per warp)
    float bs0[NT], bs1[NT];
#pragma unroll
    for (int nt = 0; nt < NT; nt++) {
        int c = bn + wn * WN + nt * 8 + lc * 2;
        bs0[nt] = bias[c];
        bs1[nt] = bias[c + 1];
    }

    // A staging registers
    const int arow = t >> 2, aseg = t & 3;
    float4 aF[8];
    uint4 aH[4];

    auto ldg_tile = [&](int m) {
        if constexpr (!AHALF) {
            const float* Ap = (const float*)Av
                + (size_t)(mbase + m * 64 + arow) * 128 + aseg * 8;
#pragma unroll
            for (int s = 0; s < 4; s++) {
                aF[2 * s]     = *(const float4*)(Ap + s * 32);
                aF[2 * s + 1] = *(const float4*)(Ap + s * 32 + 4);
            }
        } else {
            const __half* Ap = (const __half*)Av
                + (size_t)(mbase + m * 64 + arow) * 128 + aseg * 8;
#pragma unroll
            for (int s = 0; s < 4; s++)
                aH[s] = *(const uint4*)(Ap + s * 32);
        }
    };
    auto sts_tile = [&](int m) {
        uint32_t* dst = sA + (m & 1) * AB + arow * 20 + aseg * 4;
        if constexpr (!AHALF) {
#pragma unroll
            for (int s = 0; s < 4; s++) {
                uint4 v;
                v.x = h22u(__floats2half2_rn(aF[2 * s].x, aF[2 * s].y));
                v.y = h22u(__floats2half2_rn(aF[2 * s].z, aF[2 * s].w));
                v.z = h22u(__floats2half2_rn(aF[2 * s + 1].x, aF[2 * s + 1].y));
                v.w = h22u(__floats2half2_rn(aF[2 * s + 1].z, aF[2 * s + 1].w));
                *(uint4*)(dst + s * 1280) = v;
            }
        } else {
#pragma unroll
            for (int s = 0; s < 4; s++)
                *(uint4*)(dst + s * 1280) = aH[s];
        }
    };

    ldg_tile(0);

#pragma unroll 1
    for (int m = 0; m < 4; m++) {
        sts_tile(m);
        __syncthreads();
        if (m < 3) ldg_tile(m + 1);

        float acc[NT][4];
#pragma unroll
        for (int nt = 0; nt < NT; nt++)
#pragma unroll
            for (int i = 0; i < 4; i++) acc[nt][i] = 0.f;

        const uint32_t aBase = smb + (m & 1) * AB * 4 + aPat;
#pragma unroll
        for (int s = 0; s < 8; s++) {
            uint32_t af[4], bf[NT][2];
            ldm4(af, aBase + (s >> 1) * 5120 + (s & 1) * 32);
#pragma unroll
            for (int p = 0; p < NP; p++) {
                uint32_t r4[4];
                ldm4t(r4, bAddr[p] + s * 1280);
                bf[2 * p][0] = r4[0]; bf[2 * p][1] = r4[1];
                bf[2 * p + 1][0] = r4[2]; bf[2 * p + 1][1] = r4[3];
            }
#pragma unroll
            for (int nt = 0; nt < NT; nt++)
                mma16(acc[nt], af, bf[nt]);
        }

        // epilogue with bias
        const int r0 = mbase + m * 64 + wm * 16 + lr;
#pragma unroll
        for (int nt = 0; nt < NT; nt++) {
            int c = bn + wn * WN + nt * 8 + lc * 2;
            if constexpr (OUTHALF) {
                __half* Ch = (__half*)Cv;
                *(__half2*)(Ch + (size_t)r0 * N + c) =
                    __floats2half2_rn(acc[nt][0] + bs0[nt], acc[nt][1] + bs1[nt]);
                *(__half2*)(Ch + (size_t)(r0 + 8) * N + c) =
                    __floats2half2_rn(acc[nt][2] + bs0[nt], acc[nt][3] + bs1[nt]);
            } else {
                float* Cf = (float*)Cv;
                *(float2*)(Cf + (size_t)r0 * N + c) =
                    make_float2(acc[nt][0] + bs0[nt], acc[nt][1] + bs1[nt]);
                *(float2*)(Cf + (size_t)(r0 + 8) * N + c) =
                    make_float2(acc[nt][2] + bs0[nt], acc[nt][3] + bs1[nt]);
            }
        }
    }
}

// ---------------------------------------------------------------------------
// Streaming flash-style neighborhood attention (R7-validated, verbatim).
// ---------------------------------------------------------------------------
#define SQ_OFF 0
#define SK_OFF (64 * 20)
#define SV_OFF (SK_OFF + 208 * 20)
#define SM_WORDS (SV_OFF + 208 * 20)

__global__ __launch_bounds__(128)
void natten_kernel(const __half* __restrict__ qkv, const float* __restrict__ rpb)
{
    __shared__ __align__(16) uint32_t sm[SM_WORDS];
    __shared__ float rp[169];

    const int tile = blockIdx.x;             // 0..48
    const int ti = tile / 7, tj = tile % 7;
    const int h = blockIdx.y, b = blockIdx.z;
    const int i0 = ti * 8, j0 = tj * 8;
    const int r0 = min(max(i0 - 3, 0), HH - 14);
    const int c0 = min(max(j0 - 3, 0), WW - 14);
    const int tid = threadIdx.x;

    for (int e = tid; e < 169; e += 128) rp[e] = rpb[h * 169 + e];

#pragma unroll
    for (int e = tid; e < 256; e += 128) {
        int row = e >> 2, seg = e & 3;
        int qi = row >> 3, qj = row & 7;
        size_t pix = (size_t)((b * HH + i0 + qi) * WW + j0 + qj);
        *(uint4*)(sm + SQ_OFF + row * 20 + seg * 4) =
            *(const uint4*)(qkv + pix * 384 + h * 32 + seg * 8);
    }
    for (int e = tid; e < 784; e += 128) {
        int row = e >> 2, seg = e & 3;
        int r = row / 14, c = row - r * 14;
        size_t pix = (size_t)((b * HH + r0 + r) * WW + c0 + c);
        const __half* base = qkv + pix * 384 + h * 32;
        *(uint4*)(sm + SK_OFF + row * 20 + seg * 4) = *(const uint4*)(base + 128 + seg * 8);
        *(uint4*)(sm + SV_OFF + row * 20 + seg * 4) = *(const uint4*)(base + 256 + seg * 8);
    }
    for (int e = tid; e < 240; e += 128) {
        sm[SK_OFF + 3920 + e] = 0;
        sm[SV_OFF + 3920 + e] = 0;
    }
    __syncthreads();

    const int w = tid >> 5, lane = tid & 31;
    const int lr = lane >> 2, lc = lane & 3;
    const int lt = lane >> 3, rw = lane & 7;

    const uint32_t base = (uint32_t)__cvta_generic_to_shared(sm);
    const uint32_t aAddr = base + SQ_OFF * 4
        + ((w * 16 + (lt & 1) * 8 + rw) * 20 + ((lt >> 1) << 2)) * 4;
    const uint32_t kAddr = base + SK_OFF * 4
        + ((((lt >> 1) << 3) + rw) * 20 + ((lt & 1) << 2)) * 4;
    const uint32_t vAddr = base + SV_OFF * 4
        + (((((lane >> 3) & 1) << 3) + (lane & 7)) * 20 + ((lane >> 4) << 2)) * 4;

    uint32_t af0[4], af1[4];
    ldm4(af0, aAddr);
    ldm4(af1, aAddr + 32);

    const int i_lo = i0 + 2 * w, i_hi = i_lo + 1;
    const int j = j0 + lr;
    const int kri_lo = min(max(i_lo - 3, 0), HH - 7) - r0;
    const int kri_hi = min(max(i_hi - 3, 0), HH - 7) - r0;
    const int kcj = min(max(j - 3, 0), WW - 7) - c0;
    const int ci_lo = 6 - (i_lo - r0);
    const int ci_hi = 6 - (i_hi - r0);
    const int cj = 6 - (j - c0);
    const float scale = 0.17677669529663687f;   // 32^-0.5

    float out[4][4];
#pragma unroll
    for (int nt = 0; nt < 4; nt++)
#pragma unroll
        for (int i = 0; i < 4; i++) out[nt][i] = 0.f;
    float l_lo = 0.f, l_hi = 0.f;

#pragma unroll
    for (int t2 = 0; t2 < 13; t2++) {
        float sacc[2][4];
#pragma unroll
        for (int tt = 0; tt < 2; tt++)
#pragma unroll
            for (int i = 0; i < 4; i++) sacc[tt][i] = 0.f;
        {
            uint32_t r4[4];
            ldm4(r4, kAddr + t2 * 1280);
            mma16(sacc[0], af0, r4);
            mma16(sacc[1], af0, r4 + 2);
            ldm4(r4, kAddr + t2 * 1280 + 32);
            mma16(sacc[0], af1, r4);
            mma16(sacc[1], af1, r4 + 2);
        }
#pragma unroll
        for (int tt = 0; tt < 2; tt++) {
#pragma unroll
            for (int c = 0; c < 2; c++) {
                int key = (2 * t2 + tt) * 8 + 2 * lc + c;
                int kr = (key * 2341) >> 15;
                int kc = key - kr * 14;
                bool vC = (unsigned)(kc - kcj) < 7u;
                int cb = kc + cj;

                bool v1 = vC && ((unsigned)(kr - kri_lo) < 7u);
                int idx1 = min(max((kr + ci_lo) * 13 + cb, 0), 168);
                float e1 = __expf(v1 ? fmaf(sacc[tt][c], scale, rp[idx1]) : -60.f);
                sacc[tt][c] = e1;
                l_lo += e1;

                bool v2 = vC && ((unsigned)(kr - kri_hi) < 7u);
                int idx2 = min(max((kr + ci_hi) * 13 + cb, 0), 168);
                float e2 = __expf(v2 ? fmaf(sacc[tt][2 + c], scale, rp[idx2]) : -60.f);
                sacc[tt][2 + c] = e2;
                l_hi += e2;
            }
        }
        uint32_t pa[4];
        pa[0] = h22u(__floats2half2_rn(sacc[0][0], sacc[0][1]));
        pa[1] = h22u(__floats2half2_rn(sacc[0][2], sacc[0][3]));
        pa[2] = h22u(__floats2half2_rn(sacc[1][0], sacc[1][1]));
        pa[3] = h22u(__floats2half2_rn(sacc[1][2], sacc[1][3]));

        uint32_t b0[4], b1[4];
        ldm4t(b0, vAddr + t2 * 1280);
        ldm4t(b1, vAddr + t2 * 1280 + 32);
        mma16(out[0], pa, b0);
        mma16(out[1], pa, b0 + 2);
        mma16(out[2], pa, b1);
        mma16(out[3], pa, b1 + 2);
    }

    const unsigned fm = 0xffffffffu;
    l_lo += __shfl_xor_sync(fm, l_lo, 1);
    l_lo += __shfl_xor_sync(fm, l_lo, 2);
    l_hi += __shfl_xor_sync(fm, l_hi, 1);
    l_hi += __shfl_xor_sync(fm, l_hi, 2);

    const float inv_lo = __frcp_rn(l_lo);
    const float inv_hi = __frcp_rn(l_hi);
    __half* o_lo = g_att + ((size_t)((b * HH + i_lo) * WW + j)) * 128 + h * 32;
    __half* o_hi = g_att + ((size_t)((b * HH + i_hi) * WW + j)) * 128 + h * 32;
#pragma unroll
    for (int nt = 0; nt < 4; nt++) {
        *(__half2*)(o_lo + nt * 8 + 2 * lc) =
            __floats2half2_rn(out[nt][0] * inv_lo, out[nt][1] * inv_lo);
        *(__half2*)(o_hi + nt * 8 + 2 * lc) =
            __floats2half2_rn(out[nt][2] * inv_hi, out[nt][3] * inv_hi);
    }
}

// ---------------------------------------------------------------------------
// Launch
// ---------------------------------------------------------------------------
extern "C" void kernel_launch(void* const* d_in, const int* in_sizes, int n_in,
                              void* d_out, int out_size)
{
    const float* x      = (const float*)d_in[0];  // [4,56,56,128]
    const float* w_qkv  = (const float*)d_in[1];  // [128,384]
    const float* b_qkv  = (const float*)d_in[2];  // [384]
    const float* rpb    = (const float*)d_in[3];  // [4,13,13]
    const float* w_proj = (const float*)d_in[4];  // [128,128]
    const float* b_proj = (const float*)d_in[5];  // [128]
    float* out = (float*)d_out;                   // [4,56,56,128] fp32
    (void)in_sizes; (void)n_in; (void)out_size;

    __half *qkv_buf, *att_buf;
    cudaGetSymbolAddress((void**)&qkv_buf, g_qkv);
    cudaGetSymbolAddress((void**)&att_buf, g_att);

    constexpr int SMQ = (2 * 4 * 64 * 20 + 4 * 2576) * 4;   // 82176 B
    constexpr int SMP = (2 * 4 * 64 * 20 + 2 * 2576) * 4;   // 61568 B

    cudaFuncSetAttribute((const void*)gemm_col<128, false, true>,
                         cudaFuncAttributeMaxDynamicSharedMemorySize, SMQ);
    cudaFuncSetAttribute((const void*)gemm_col<64, true, false>,
                         cudaFuncAttributeMaxDynamicSharedMemorySize, SMP);

    // 1) QKV projection: [12544,128] @ [128,384] + b_qkv -> half
    gemm_col<128, false, true><<<dim3(3, 49), 256, SMQ>>>(
        x, w_qkv, b_qkv, qkv_buf, 384);

    // 2) Neighborhood attention (streaming tensor-core flash)
    natten_kernel<<<dim3(49, 4, 4), 128>>>(qkv_buf, rpb);

    // 3) Output projection: [12544,128] @ [128,128] + b_proj -> float
    gemm_col<64, true, false><<<dim3(2, 49), 256, SMP>>>(
        att_buf, w_proj, b_proj, out, 128);
}